// round 2
// baseline (speedup 1.0000x reference)
#include <cuda_runtime.h>
#include <cstddef>

// Legendre-feature GEMM, fused:
//   out[b,o] = sum_{f=0..8} sum_{i=0..511} P_f(x[b,i]) * W[f,i,o] + bias[o]
// B=16384, I=512, O=512, F=9  ->  GEMM with K = 9*512 = 4608, A computed on the fly.

#define BM 128
#define BN 128
#define KC 8                 // I-elements per chunk
#define FDEG 9               // degrees 0..8
#define KK (KC * FDEG)       // 72 k-steps per chunk
#define AS_PITCH 132         // padded pitch for A-transposed tile (bank-conflict-free)
#define NTHREADS 256

__global__ __launch_bounds__(NTHREADS, 2)
void legendre_sgemm_kernel(const float* __restrict__ x,
                           const float* __restrict__ w,
                           const float* __restrict__ bias,
                           float* __restrict__ out,
                           int I, int O)
{
    extern __shared__ float smem[];
    float* As = smem;                      // [KK][AS_PITCH]  A^T tile (k-major rows)
    float* Ws = smem + KK * AS_PITCH;      // [KK][BN]        W tile

    const int tid = threadIdx.x;
    const int tx  = tid & 15;              // output-col direction (8 cols each)
    const int ty  = tid >> 4;              // output-row direction (8 rows each)
    const int bm  = blockIdx.y * BM;
    const int bn  = blockIdx.x * BN;

    float acc[8][8];
    #pragma unroll
    for (int i = 0; i < 8; ++i)
        #pragma unroll
        for (int j = 0; j < 8; ++j)
            acc[i][j] = 0.0f;

    // Each thread owns 4 (row, i) pairs of the x-chunk for the poly recurrence.
    const int p0 = tid * 4;                // 0..1020 over 128*8 = 1024 pairs
    const int am = p0 >> 3;                // row within tile: 0..127
    const int ai = p0 & 7;                 // i within chunk: 0 or 4
    const float* xrow = x + (size_t)(bm + am) * I;

    for (int i0 = 0; i0 < I; i0 += KC) {
        __syncthreads();   // previous iteration's smem reads done

        // ---- load 9 W tiles: row kk = f*8 + ii  <-  w[f][i0+ii][bn .. bn+127]
        #pragma unroll
        for (int r = 0; r < 9; ++r) {
            int idx  = tid + (r << 8);     // 0..2303 float4 slots (72*32)
            int row  = idx >> 5;           // 0..71
            int col  = (idx & 31) << 2;    // 0..124
            int f    = row >> 3;
            int ii   = row & 7;
            const float4 wv = *(const float4*)(w + ((size_t)f * I + (i0 + ii)) * O + bn + col);
            *(float4*)(Ws + row * BN + col) = wv;
        }

        // ---- compute Legendre features for this x-chunk into As (transposed)
        {
            float4 xv = *(const float4*)(xrow + i0 + ai);
            float xs[4] = {xv.x, xv.y, xv.z, xv.w};
            #pragma unroll
            for (int j = 0; j < 4; ++j) {
                const int col = ai + j;    // i within chunk
                float xx  = xs[j];
                float pm2 = 1.0f;
                float pm1 = xx;
                As[(0 * KC + col) * AS_PITCH + am] = 1.0f;
                As[(1 * KC + col) * AS_PITCH + am] = xx;
                #pragma unroll
                for (int n = 2; n <= 8; ++n) {
                    const float c1 = (2.0f * n - 1.0f) / (float)n;
                    const float c2 = ((float)n - 1.0f) / (float)n;
                    float pn = c1 * xx * pm1 - c2 * pm2;
                    As[(n * KC + col) * AS_PITCH + am] = pn;
                    pm2 = pm1; pm1 = pn;
                }
            }
        }
        __syncthreads();

        // ---- 72 rank-1 updates
        #pragma unroll 8
        for (int kk = 0; kk < KK; ++kk) {
            float a[8], b[8];
            *(float4*)(a)     = *(const float4*)(As + kk * AS_PITCH + ty * 8);
            *(float4*)(a + 4) = *(const float4*)(As + kk * AS_PITCH + ty * 8 + 4);
            *(float4*)(b)     = *(const float4*)(Ws + kk * BN + tx * 8);
            *(float4*)(b + 4) = *(const float4*)(Ws + kk * BN + tx * 8 + 4);
            #pragma unroll
            for (int i = 0; i < 8; ++i)
                #pragma unroll
                for (int j = 0; j < 8; ++j)
                    acc[i][j] = fmaf(a[i], b[j], acc[i][j]);
        }
    }

    // ---- epilogue: add bias, store
    float bb[8];
    *(float4*)(bb)     = *(const float4*)(bias + bn + tx * 8);
    *(float4*)(bb + 4) = *(const float4*)(bias + bn + tx * 8 + 4);
    #pragma unroll
    for (int i = 0; i < 8; ++i) {
        float* orow = out + (size_t)(bm + ty * 8 + i) * O + bn + tx * 8;
        float4 v0 = make_float4(acc[i][0] + bb[0], acc[i][1] + bb[1],
                                acc[i][2] + bb[2], acc[i][3] + bb[3]);
        float4 v1 = make_float4(acc[i][4] + bb[4], acc[i][5] + bb[5],
                                acc[i][6] + bb[6], acc[i][7] + bb[7]);
        *(float4*)(orow)     = v0;
        *(float4*)(orow + 4) = v1;
    }
}

extern "C" void kernel_launch(void* const* d_in, const int* in_sizes, int n_in,
                              void* d_out, int out_size)
{
    const float* x    = (const float*)d_in[0];   // [B, 512]
    const float* w    = (const float*)d_in[1];   // [9, 512, 512]
    const float* bias = (const float*)d_in[2];   // [512]
    float* out        = (float*)d_out;           // [B, 512]

    const int I = 512;
    const int O = 512;
    const int B = in_sizes[0] / I;               // 16384

    dim3 grid(O / BN, B / BM);                   // (4, 128)
    size_t smem_bytes = (size_t)(KK * AS_PITCH + KK * BN) * sizeof(float);  // ~74.9 KB

    cudaFuncSetAttribute(legendre_sgemm_kernel,
                         cudaFuncAttributeMaxDynamicSharedMemorySize,
                         (int)smem_bytes);

    legendre_sgemm_kernel<<<grid, NTHREADS, smem_bytes>>>(x, w, bias, out, I, O);
}

// round 5
// speedup vs baseline: 2.4899x; 2.4899x over previous
#include <cuda_runtime.h>
#include <cstdint>
#include <cstddef>

// ============================================================================
// RecurrentLegendreLayer via 3xBF16-split mma.sync (HMMA) GEMM.
//   out[b,o] = sum_{f,i} P_f(x[b,i]) * W[f,i,o] + bias[o]
//   M=16384, N=512, K=4608.  v = vh(bf16) + vl(bf16);
//   out ~= Ah*Bh + Al*Bh + Ah*Bl   (rel err ~1e-5)
// K order: chunk c = ib*9 + f, chunk covers (degree f, i in [ib*32, ib*32+32))
// ============================================================================

#define FDEG    9
#define NCHUNK  144
#define BM      128
#define BN      256
#define NTHR    512

// smem layout (bytes). A: [hl|buf] tiles of [128 rows][80B pitch] bf16.
//                      B: [hl|buf] tiles of [32 rows][528B pitch] bf16.
#define APITCH  80
#define ATILE   10240
#define BPITCH  528
#define BTILE   16896
#define SM_A    0
#define SM_B    40960
#define SMEM_TOTAL 108544

// prepared W: bf16, halves index = ((c*2+hl)*32 + k)*512 + n
__device__ uint32_t g_B[2359296];   // 9.4 MB

// ---------------------------------------------------------------- helpers ---
__device__ __forceinline__ uint32_t smem_u32(const void* p) {
    return (uint32_t)__cvta_generic_to_shared(p);
}
__device__ __forceinline__ void cp_async16(uint32_t dst, const void* src) {
    asm volatile("cp.async.cg.shared.global [%0], [%1], 16;"
                 :: "r"(dst), "l"(__cvta_generic_to_global(src)));
}
__device__ __forceinline__ void cp_commit() { asm volatile("cp.async.commit_group;"); }
__device__ __forceinline__ void cp_wait0() {
    asm volatile("cp.async.wait_group 0;" ::: "memory");
}
__device__ __forceinline__ void ldsm_x4(uint32_t* r, uint32_t addr) {
    asm volatile("ldmatrix.sync.aligned.m8n8.x4.shared.b16 {%0,%1,%2,%3}, [%4];"
                 : "=r"(r[0]), "=r"(r[1]), "=r"(r[2]), "=r"(r[3]) : "r"(addr));
}
__device__ __forceinline__ void ldsm_x4_t(uint32_t* r, uint32_t addr) {
    asm volatile("ldmatrix.sync.aligned.m8n8.x4.trans.shared.b16 {%0,%1,%2,%3}, [%4];"
                 : "=r"(r[0]), "=r"(r[1]), "=r"(r[2]), "=r"(r[3]) : "r"(addr));
}
__device__ __forceinline__ void mma16816(float* c, const uint32_t* a,
                                         uint32_t b0, uint32_t b1) {
    asm volatile(
        "mma.sync.aligned.m16n8k16.row.col.f32.bf16.bf16.f32 "
        "{%0,%1,%2,%3}, {%4,%5,%6,%7}, {%8,%9}, {%0,%1,%2,%3};"
        : "+f"(c[0]), "+f"(c[1]), "+f"(c[2]), "+f"(c[3])
        : "r"(a[0]), "r"(a[1]), "r"(a[2]), "r"(a[3]), "r"(b0), "r"(b1));
}
__device__ __forceinline__ uint32_t pack_lo_bf16(float a0, float a1) {
    uint32_t d;
    asm("cvt.rn.bf16x2.f32 %0, %1, %2;" : "=r"(d) : "f"(a1), "f"(a0));
    return d;
}

// ---------------------------------------------------------------- prepass ---
__global__ void leg_prep_kernel(const float* __restrict__ w) {
    uint32_t t = blockIdx.x * 256 + threadIdx.x;       // word id, 2359296 total
    uint32_t n2 = t & 255;                             // n pair: n = 2*n2
    uint32_t q  = t >> 8;                              // row 0..9215
    uint32_t k  = q & 31;
    uint32_t hl = (q >> 5) & 1;
    uint32_t c  = q >> 6;
    uint32_t f  = c % FDEG, ib = c / FDEG;
    size_t widx = ((size_t)(f * 512 + ib * 32 + k)) * 512 + n2 * 2;
    float w0 = w[widx], w1 = w[widx + 1];
    uint32_t b0 = __float_as_uint(w0) + 0x8000u;
    uint32_t b1 = __float_as_uint(w1) + 0x8000u;
    uint32_t word;
    if (hl == 0) {
        word = (b0 >> 16) | (b1 & 0xffff0000u);
    } else {
        float h0 = __uint_as_float(b0 & 0xffff0000u);
        float h1 = __uint_as_float(b1 & 0xffff0000u);
        word = pack_lo_bf16(w0 - h0, w1 - h1);
    }
    g_B[t] = word;
}

// ------------------------------------------------------------ main kernel ---
__global__ __launch_bounds__(NTHR, 1)
void leg_mma_kernel(const float* __restrict__ x,
                    const float* __restrict__ bias,
                    float* __restrict__ out)
{
    extern __shared__ char sm[];
    const uint32_t sb = smem_u32(sm);
    const int tid    = threadIdx.x;
    const int lane   = tid & 31;
    const int wid    = tid >> 5;
    const int warp_m = wid & 3;          // 4 M-warps  (32 rows each)
    const int warp_n = wid >> 2;         // 4 N-warps  (64 cols each)
    const int bn = blockIdx.x * BN;
    const int bm = blockIdx.y * BM;

    float acc[2][8][4];
    #pragma unroll
    for (int a = 0; a < 2; ++a)
        #pragma unroll
        for (int b = 0; b < 8; ++b)
            #pragma unroll
            for (int d = 0; d < 4; ++d) acc[a][b][d] = 0.0f;

    // Legendre state: thread owns row am = tid/4, i-range ai0..ai0+8
    const int am  = tid >> 2;
    const int ai0 = (tid & 3) * 8;
    float xv[8], pm1[8], pm2[8];

    // precomputed ldmatrix lane addresses (offsets within a tile)
    // A: row = warp_m*32 + mf*16 + (lane&15); colbyte = k16*32 + (lane>>4)*16
    const uint32_t aRow = (uint32_t)(warp_m * 32 + (lane & 15)) * APITCH
                        + (uint32_t)(lane >> 4) * 16;
    // B: row = k16*16 + (lane&15); colbyte = (warp_n*64 + nf*16 + (lane>>4)*8)*2
    const uint32_t bRow = (uint32_t)(lane & 15) * BPITCH
                        + ((uint32_t)(warp_n * 64) + (uint32_t)(lane >> 4) * 8) * 2;

    // ---- B chunk loader: 4 x 16B cp.async per thread (64KB total per chunk)
    auto issue_load = [&](int c, int buf) {
        #pragma unroll
        for (int j = 0; j < 4; ++j) {
            int seg = tid + j * NTHR;
            int hl  = seg >> 10;
            int r   = seg & 1023;
            int k   = r >> 5;
            int n16 = r & 31;
            uint32_t dst = sb + SM_B + (uint32_t)(buf * 2 + hl) * BTILE
                         + (uint32_t)k * BPITCH + (uint32_t)n16 * 16;
            const char* src = (const char*)g_B
                + (((size_t)(c * 2 + hl) * 32 + k) * 512 + bn + n16 * 8) * 2;
            cp_async16(dst, src);
        }
        cp_commit();
    };

    issue_load(0, 0);

    for (int s = 0; s < NCHUNK; ++s) {
        const int buf = s & 1;
        cp_wait0();
        __syncthreads();                 // B(s) visible; mma(s-1) done everywhere
        if (s + 1 < NCHUNK) issue_load(s + 1, (s + 1) & 1);

        // ---- compute A(s): one Legendre degree, split hi/lo, store to smem
        {
            const int f  = s % FDEG;
            const int ib = s / FDEG;
            float p[8];
            if (f == 0) {
                const float4* xp = (const float4*)(x + (size_t)(bm + am) * 512
                                                   + ib * 32 + ai0);
                float4 v0 = xp[0], v1 = xp[1];
                xv[0]=v0.x; xv[1]=v0.y; xv[2]=v0.z; xv[3]=v0.w;
                xv[4]=v1.x; xv[5]=v1.y; xv[6]=v1.z; xv[7]=v1.w;
                #pragma unroll
                for (int j = 0; j < 8; ++j) p[j] = 1.0f;
            } else if (f == 1) {
                #pragma unroll
                for (int j = 0; j < 8; ++j) { p[j] = xv[j]; pm2[j] = 1.0f; pm1[j] = xv[j]; }
            } else {
                const float fv = (float)f;
                const float c1 = (2.0f * fv - 1.0f) / fv;
                const float c2 = (fv - 1.0f) / fv;
                #pragma unroll
                for (int j = 0; j < 8; ++j) {
                    float pn = c1 * xv[j] * pm1[j] - c2 * pm2[j];
                    pm2[j] = pm1[j]; pm1[j] = pn; p[j] = pn;
                }
            }
            uint32_t hiw[4], low[4];
            #pragma unroll
            for (int j2 = 0; j2 < 4; ++j2) {
                float a0 = p[2 * j2], a1 = p[2 * j2 + 1];
                uint32_t r0 = __float_as_uint(a0) + 0x8000u;
                uint32_t r1 = __float_as_uint(a1) + 0x8000u;
                hiw[j2] = (r0 >> 16) | (r1 & 0xffff0000u);
                float h0 = __uint_as_float(r0 & 0xffff0000u);
                float h1 = __uint_as_float(r1 & 0xffff0000u);
                low[j2] = pack_lo_bf16(a0 - h0, a1 - h1);
            }
            uint32_t aaddr = sb + SM_A + (uint32_t)(buf * 2) * ATILE
                           + (uint32_t)am * APITCH + (uint32_t)ai0 * 2;
            asm volatile("st.shared.v4.b32 [%0], {%1,%2,%3,%4};"
                         :: "r"(aaddr), "r"(hiw[0]), "r"(hiw[1]), "r"(hiw[2]), "r"(hiw[3]));
            asm volatile("st.shared.v4.b32 [%0], {%1,%2,%3,%4};"
                         :: "r"(aaddr + ATILE), "r"(low[0]), "r"(low[1]), "r"(low[2]), "r"(low[3]));
        }
        __syncthreads();                 // A(s) visible

        // ---- 3-pass MMA over chunk s
        const uint32_t aHi = sb + SM_A + (uint32_t)(buf * 2) * ATILE + aRow;
        const uint32_t aLo = aHi + ATILE;
        const uint32_t bHi = sb + SM_B + (uint32_t)(buf * 2) * BTILE + bRow;
        const uint32_t bLo = bHi + BTILE;

        #pragma unroll
        for (int k16 = 0; k16 < 2; ++k16) {
            const uint32_t aOff = (uint32_t)k16 * 32;
            const uint32_t bOff = (uint32_t)(k16 * 16) * BPITCH;
            uint32_t ah[2][4], al[2][4], bb[4][4];

            ldsm_x4(ah[0], aHi + aOff);
            ldsm_x4(ah[1], aHi + aOff + 16 * APITCH);
            #pragma unroll
            for (int nf = 0; nf < 4; ++nf) ldsm_x4_t(bb[nf], bHi + bOff + nf * 32);
            #pragma unroll
            for (int mf = 0; mf < 2; ++mf)
                #pragma unroll
                for (int nf = 0; nf < 4; ++nf) {
                    mma16816(acc[mf][nf * 2 + 0], ah[mf], bb[nf][0], bb[nf][1]);
                    mma16816(acc[mf][nf * 2 + 1], ah[mf], bb[nf][2], bb[nf][3]);
                }

            ldsm_x4(al[0], aLo + aOff);
            ldsm_x4(al[1], aLo + aOff + 16 * APITCH);
            #pragma unroll
            for (int mf = 0; mf < 2; ++mf)
                #pragma unroll
                for (int nf = 0; nf < 4; ++nf) {
                    mma16816(acc[mf][nf * 2 + 0], al[mf], bb[nf][0], bb[nf][1]);
                    mma16816(acc[mf][nf * 2 + 1], al[mf], bb[nf][2], bb[nf][3]);
                }

            #pragma unroll
            for (int nf = 0; nf < 4; ++nf) ldsm_x4_t(bb[nf], bLo + bOff + nf * 32);
            #pragma unroll
            for (int mf = 0; mf < 2; ++mf)
                #pragma unroll
                for (int nf = 0; nf < 4; ++nf) {
                    mma16816(acc[mf][nf * 2 + 0], ah[mf], bb[nf][0], bb[nf][1]);
                    mma16816(acc[mf][nf * 2 + 1], ah[mf], bb[nf][2], bb[nf][3]);
                }
        }
    }

    // ---- epilogue: bias add + store (float2 per 8-col fragment half)
    const int r0 = bm + warp_m * 32 + (lane >> 2);
    const int c0 = bn + warp_n * 64 + (lane & 3) * 2;
    #pragma unroll
    for (int mf = 0; mf < 2; ++mf) {
        #pragma unroll
        for (int nf = 0; nf < 8; ++nf) {
            const int row = r0 + mf * 16;
            const int col = c0 + nf * 8;
            const float2 bv = *(const float2*)(bias + col);
            float2 v0, v1;
            v0.x = acc[mf][nf][0] + bv.x;  v0.y = acc[mf][nf][1] + bv.y;
            v1.x = acc[mf][nf][2] + bv.x;  v1.y = acc[mf][nf][3] + bv.y;
            *(float2*)(out + (size_t)row * 512 + col)       = v0;
            *(float2*)(out + (size_t)(row + 8) * 512 + col) = v1;
        }
    }
}

// ------------------------------------------------------------------ launch --
extern "C" void kernel_launch(void* const* d_in, const int* in_sizes, int n_in,
                              void* d_out, int out_size)
{
    const float* x    = (const float*)d_in[0];   // [B, 512]
    const float* w    = (const float*)d_in[1];   // [9, 512, 512]
    const float* bias = (const float*)d_in[2];   // [512]
    float* out        = (float*)d_out;           // [B, 512]

    const int B = in_sizes[0] / 512;             // 16384

    cudaFuncSetAttribute(leg_mma_kernel,
                         cudaFuncAttributeMaxDynamicSharedMemorySize,
                         SMEM_TOTAL);

    leg_prep_kernel<<<9216, 256>>>(w);           // 2359296 words

    dim3 grid(512 / BN, B / BM);                 // (2, 128)
    leg_mma_kernel<<<grid, NTHR, SMEM_TOTAL>>>(x, bias, out);
}